// round 1
// baseline (speedup 1.0000x reference)
#include <cuda_runtime.h>
#include <math.h>

// Problem constants
#define Bb 8
#define Nn 256
#define Kk 128
#define Hh 32
#define Dd 768

// Output layout: [gbias B*H*N*N][merge B*N*D][delta_pos B*N*N*3]
#define OFF_GB 0
#define OFF_MERGE (Bb*Hh*Nn*Nn)              // 16777216
#define OFF_DP    (OFF_MERGE + Bb*Nn*Dd)     // 18350080

// Scratch for masked edge-feature sums: [B*N, K]
__device__ float g_sum_ef[Bb*Nn*Kk];

__device__ __forceinline__ float gelu_exact(float v) {
    return 0.5f * v * (1.0f + erff(v * 0.70710678118654752f));
}

// Shared memory layout (floats)
#define SOFF_W1   0        // 16384  w1s[k*128+h]
#define SOFF_W2   16384    // 4096   w2s[k*32+h2]
#define SOFF_EFT  20480    // 16384  efT[k*128+j]
#define SOFF_HIDT 36864    // 16384  hidT[h*128+j]
#define SOFF_XG   53248    // 256
#define SOFF_MK   53504    // 256
#define SOFF_SUM  53760    // 128
#define SOFF_MEAN 53888    // 128
#define SOFF_ISTD 54016    // 128
#define SOFF_COEF 54144    // 128
#define SOFF_B1   54272    // 128
#define SOFF_B2   54400    // 32
#define SMEM_FLOATS 54432  // 217728 bytes

extern "C" __global__ void __launch_bounds__(256, 1)
mol3d_main(const float* __restrict__ pos, const int* __restrict__ x,
           const int* __restrict__ nte, const float* __restrict__ means,
           const float* __restrict__ stds, const float* __restrict__ mul_w,
           const float* __restrict__ bias_w, const float* __restrict__ w1,
           const float* __restrict__ b1, const float* __restrict__ w2,
           const float* __restrict__ b2, float* __restrict__ out)
{
    extern __shared__ float sm[];
    float* w1s  = sm + SOFF_W1;
    float* w2s  = sm + SOFF_W2;
    float* efT  = sm + SOFF_EFT;
    float* hidT = sm + SOFF_HIDT;
    float* xg   = sm + SOFF_XG;
    float* mkf  = sm + SOFF_MK;
    float* sums = sm + SOFF_SUM;
    float* meanv= sm + SOFF_MEAN;
    float* istdv= sm + SOFF_ISTD;
    float* coefv= sm + SOFF_COEF;
    float* b1s  = sm + SOFF_B1;
    float* b2s  = sm + SOFF_B2;

    const int tid = threadIdx.x;
    const int b = blockIdx.x >> 8;
    const int i = blockIdx.x & 255;

    // ---- load weights into smem ----
    {
        const float4* w1g = (const float4*)w1;
        float4* w1d = (float4*)w1s;
        #pragma unroll 4
        for (int idx = tid; idx < (128*128)/4; idx += 256) w1d[idx] = w1g[idx];
        const float4* w2g = (const float4*)w2;
        float4* w2d = (float4*)w2s;
        #pragma unroll 2
        for (int idx = tid; idx < (128*32)/4; idx += 256) w2d[idx] = w2g[idx];
    }
    if (tid < 128) {
        float s = fabsf(stds[tid]) + 0.01f;
        float a = sqrtf(2.0f * 3.14159f);
        istdv[tid] = 1.0f / s;
        coefv[tid] = 1.0f / (a * s);
        meanv[tid] = means[tid];
        b1s[tid]   = b1[tid];
        sums[tid]  = 0.0f;
    }
    if (tid < 32) b2s[tid] = b2[tid];

    // ---- phase 0: per-j dist, delta_pos, xg, mask ----
    {
        const int j = tid;
        float pix = pos[(b*Nn + i)*3 + 0];
        float piy = pos[(b*Nn + i)*3 + 1];
        float piz = pos[(b*Nn + i)*3 + 2];
        float dx = pos[(b*Nn + j)*3 + 0] - pix;
        float dy = pos[(b*Nn + j)*3 + 1] - piy;
        float dz = pos[(b*Nn + j)*3 + 2] - piz;
        float dist = sqrtf(dx*dx + dy*dy + dz*dz + 1e-12f);
        float rn = 1.0f / (dist + 1e-5f);
        int dpb = OFF_DP + ((b*Nn + i)*Nn + j)*3;
        out[dpb + 0] = dx * rn;
        out[dpb + 1] = dy * rn;
        out[dpb + 2] = dz * rn;

        int eb = (((b*Nn + i)*Nn) + j)*2;
        int e0 = nte[eb], e1 = nte[eb + 1];
        float mu = mul_w[e0] + mul_w[e1];
        float bi = bias_w[e0] + bias_w[e1];
        xg[j] = mu * dist + bi;

        const int* xp = x + (b*Nn + j)*9;
        bool m = true;
        #pragma unroll
        for (int q = 0; q < 9; q++) m = m && (xp[q] == 0);
        mkf[j] = m ? 1.0f : 0.0f;
    }
    __syncthreads();

    const int ty = tid >> 4;        // 0..15, j-group of 8
    const int tx = tid & 15;        // 0..15, h-group of 8
    const int jg = tid & 63;        // 0..63, j-group of 2 (GEMM2)
    const int hg = tid >> 6;        // 0..3,  h2-group of 8 (GEMM2)
    const float NEG_INF = __int_as_float(0xff800000);

    for (int jt = 0; jt < 2; jt++) {
        const int j0 = jt * 128;

        // ---- gaussian edge features: efT[k][j], k-major ----
        {
            const int jl = tid & 127;
            const int kh = tid >> 7;
            const float xv = xg[j0 + jl];
            #pragma unroll 8
            for (int kk = 0; kk < 64; kk++) {
                int k = kh*64 + kk;
                float t = (xv - meanv[k]) * istdv[k];
                efT[k*128 + jl] = coefv[k] * __expf(-0.5f * t * t);
            }
        }
        __syncthreads();

        // ---- masked j-sum of edge features (threads < 128, diagonal read) ----
        if (tid < 128) {
            float acc = 0.0f;
            const float* row = &efT[tid*128];
            #pragma unroll 4
            for (int jj = 0; jj < 128; jj++) {
                int jl = (tid + jj) & 127;
                acc += row[jl] * (1.0f - mkf[j0 + jl]);
            }
            sums[tid] += acc;
        }

        // ---- GEMM1: hid[128j x 128h] = efT^T @ w1 + b1, 8x8 register tiles ----
        float acc[8][8];
        #pragma unroll
        for (int u = 0; u < 8; u++)
            #pragma unroll
            for (int v = 0; v < 8; v++) acc[u][v] = b1s[tx*8 + v];

        #pragma unroll 4
        for (int k = 0; k < 128; k++) {
            const float* efr = &efT[k*128 + ty*8];
            float4 a0 = *(const float4*)(efr);
            float4 a1 = *(const float4*)(efr + 4);
            const float* wr = &w1s[k*128 + tx*8];
            float4 c0 = *(const float4*)(wr);
            float4 c1 = *(const float4*)(wr + 4);
            float av[8] = {a0.x, a0.y, a0.z, a0.w, a1.x, a1.y, a1.z, a1.w};
            float bv[8] = {c0.x, c0.y, c0.z, c0.w, c1.x, c1.y, c1.z, c1.w};
            #pragma unroll
            for (int u = 0; u < 8; u++)
                #pragma unroll
                for (int v = 0; v < 8; v++)
                    acc[u][v] += av[u] * bv[v];
        }

        // gelu + store transposed: hidT[h][j]
        #pragma unroll
        for (int hh = 0; hh < 8; hh++) {
            float4 v0, v1;
            v0.x = gelu_exact(acc[0][hh]); v0.y = gelu_exact(acc[1][hh]);
            v0.z = gelu_exact(acc[2][hh]); v0.w = gelu_exact(acc[3][hh]);
            v1.x = gelu_exact(acc[4][hh]); v1.y = gelu_exact(acc[5][hh]);
            v1.z = gelu_exact(acc[6][hh]); v1.w = gelu_exact(acc[7][hh]);
            float* hr = &hidT[(tx*8 + hh)*128 + ty*8];
            *(float4*)(hr)     = v0;
            *(float4*)(hr + 4) = v1;
        }
        __syncthreads();

        // ---- GEMM2: gbf[128j x 32h2] = hid @ w2 + b2, 2x8 tiles ----
        float acc2[2][8];
        #pragma unroll
        for (int v = 0; v < 8; v++) {
            float bb = b2s[hg*8 + v];
            acc2[0][v] = bb; acc2[1][v] = bb;
        }
        #pragma unroll 4
        for (int h = 0; h < 128; h++) {
            float2 av = *(const float2*)&hidT[h*128 + jg*2];
            const float* wr = &w2s[h*32 + hg*8];
            float4 c0 = *(const float4*)(wr);
            float4 c1 = *(const float4*)(wr + 4);
            float bv[8] = {c0.x, c0.y, c0.z, c0.w, c1.x, c1.y, c1.z, c1.w};
            #pragma unroll
            for (int v = 0; v < 8; v++) {
                acc2[0][v] += av.x * bv[v];
                acc2[1][v] += av.y * bv[v];
            }
        }

        // write gbias[b][h2][i][j], masked -inf on padded j
        const float m0 = mkf[j0 + jg*2 + 0];
        const float m1 = mkf[j0 + jg*2 + 1];
        #pragma unroll
        for (int hh = 0; hh < 8; hh++) {
            int h2 = hg*8 + hh;
            float v0 = (m0 > 0.5f) ? NEG_INF : acc2[0][hh];
            float v1 = (m1 > 0.5f) ? NEG_INF : acc2[1][hh];
            int off = OFF_GB + (((b*Hh + h2)*Nn + i)*Nn + j0 + jg*2);
            *(float2*)&out[off] = make_float2(v0, v1);
        }
        __syncthreads();   // efT/hidT reused next tile
    }

    if (tid < 128) g_sum_ef[(b*Nn + i)*Kk + tid] = sums[tid];
}

// merge_edge_features = sum_ef @ edge_w + edge_b  ([2048,128] @ [128,768])
extern "C" __global__ void __launch_bounds__(256, 4)
mol3d_merge(const float* __restrict__ edge_w, const float* __restrict__ edge_b,
            float* __restrict__ out)
{
    __shared__ float sT[128*16];   // [k][r], 16 rows per block
    const int tid = threadIdx.x;
    const int r0 = blockIdx.x * 16;

    for (int idx = tid; idx < 16*128; idx += 256) {
        int r = idx >> 7, k = idx & 127;
        sT[k*16 + r] = g_sum_ef[(r0 + r)*128 + k];
    }
    __syncthreads();

    #pragma unroll
    for (int dp = 0; dp < 3; dp++) {
        const int d = tid + dp*256;
        const float bb = edge_b[d];
        float acc[16];
        #pragma unroll
        for (int r = 0; r < 16; r++) acc[r] = bb;

        #pragma unroll 4
        for (int k = 0; k < 128; k++) {
            float w = edge_w[k*768 + d];
            const float* sr = &sT[k*16];
            float4 s0 = *(const float4*)(sr);
            float4 s1 = *(const float4*)(sr + 4);
            float4 s2 = *(const float4*)(sr + 8);
            float4 s3 = *(const float4*)(sr + 12);
            acc[0]  += s0.x*w; acc[1]  += s0.y*w; acc[2]  += s0.z*w; acc[3]  += s0.w*w;
            acc[4]  += s1.x*w; acc[5]  += s1.y*w; acc[6]  += s1.z*w; acc[7]  += s1.w*w;
            acc[8]  += s2.x*w; acc[9]  += s2.y*w; acc[10] += s2.z*w; acc[11] += s2.w*w;
            acc[12] += s3.x*w; acc[13] += s3.y*w; acc[14] += s3.z*w; acc[15] += s3.w*w;
        }
        #pragma unroll
        for (int r = 0; r < 16; r++)
            out[OFF_MERGE + (r0 + r)*768 + d] = acc[r];
    }
}

extern "C" void kernel_launch(void* const* d_in, const int* in_sizes, int n_in,
                              void* d_out, int out_size)
{
    const float* pos    = (const float*)d_in[0];
    const int*   x      = (const int*)  d_in[1];
    const int*   nte    = (const int*)  d_in[2];
    const float* means  = (const float*)d_in[3];
    const float* stds   = (const float*)d_in[4];
    const float* mul_w  = (const float*)d_in[5];
    const float* bias_w = (const float*)d_in[6];
    const float* w1     = (const float*)d_in[7];
    const float* b1     = (const float*)d_in[8];
    const float* w2     = (const float*)d_in[9];
    const float* b2     = (const float*)d_in[10];
    const float* edge_w = (const float*)d_in[11];
    const float* edge_b = (const float*)d_in[12];
    float* out = (float*)d_out;

    const int smem_bytes = SMEM_FLOATS * 4;   // 217728
    cudaFuncSetAttribute((const void*)mol3d_main,
                         cudaFuncAttributeMaxDynamicSharedMemorySize, smem_bytes);

    mol3d_main<<<Bb*Nn, 256, smem_bytes>>>(pos, x, nte, means, stds, mul_w,
                                           bias_w, w1, b1, w2, b2, out);
    mol3d_merge<<<(Bb*Nn)/16, 256>>>(edge_w, edge_b, out);
}

// round 5
// speedup vs baseline: 1.1113x; 1.1113x over previous
#include <cuda_runtime.h>
#include <cuda_bf16.h>
#include <math.h>
#include <stdint.h>

// Problem constants
#define Bb 8
#define Nn 256
#define Kk 128
#define Hh 32
#define Dd 768

// Output layout: [gbias B*H*N*N][merge B*N*D][delta_pos B*N*N*3]
#define OFF_GB 0
#define OFF_MERGE (Bb*Hh*Nn*Nn)              // 16777216
#define OFF_DP    (OFF_MERGE + Bb*Nn*Dd)     // 18350080

// Scratch for masked edge-feature sums: [B*N, K]
__device__ float g_sum_ef[Bb*Nn*Kk];

// ---------------- packed f32x2 helpers ----------------
#define FMA2(acc, a, b) \
    asm("fma.rn.f32x2 %0, %1, %2, %0;" : "+l"(acc) : "l"(a), "l"(b))
#define PACK2(out, v) \
    asm("mov.b64 %0, {%1, %1};" : "=l"(out) : "r"(__float_as_uint(v)))

__device__ __forceinline__ float2 u2f(uint64_t v) {
    float2 r;
    r.x = __uint_as_float((uint32_t)v);
    r.y = __uint_as_float((uint32_t)(v >> 32));
    return r;
}

// ---------------- gelu lerp table ----------------
#define GVMIN (-6.0f)
#define GSTEP (12.0f/1024.0f)
#define GINV  (1024.0f/12.0f)

__device__ __forceinline__ float gelu_tab(float v, const float2* gtab) {
    float t = (v - GVMIN) * GINV;
    int idx = (int)t;
    idx = idx < 0 ? 0 : (idx > 1023 ? 1023 : idx);
    float frac = t - (float)idx;
    float2 e = gtab[idx];
    return v * (e.x + frac * e.y);   // v * Phi(v)
}

// Shared memory layout (float offsets)
#define SOFF_W1   0        // 16384  w1s[k*128+h]
#define SOFF_W2   16384    // 4096   w2s[k*32+h2]
#define SOFF_EFT  20480    // 16384  efT[k*128+j]
#define SOFF_HIDT 36864    // 16384  hidT[h*128+j]
#define SOFF_GTAB 53248    // 2048   (1024 x float2)
#define SOFF_XG   55296    // 256
#define SOFF_MK   55552    // 256
#define SOFF_SUM  55808    // 128
#define SOFF_MEAN 55936    // 128
#define SOFF_ISTD 56064    // 128
#define SOFF_COEF 56192    // 128
#define SOFF_B1   56320    // 128
#define SOFF_B2   56448    // 32
#define SMEM_FLOATS 56480  // 225920 bytes

extern "C" __global__ void __launch_bounds__(256, 1)
mol3d_main(const float* __restrict__ pos, const int* __restrict__ x,
           const int* __restrict__ nte, const float* __restrict__ means,
           const float* __restrict__ stds, const float* __restrict__ mul_w,
           const float* __restrict__ bias_w, const float* __restrict__ w1,
           const float* __restrict__ b1, const float* __restrict__ w2,
           const float* __restrict__ b2, float* __restrict__ out)
{
    extern __shared__ float sm[];
    float* w1s  = sm + SOFF_W1;
    float* w2s  = sm + SOFF_W2;
    float* efT  = sm + SOFF_EFT;
    float* hidT = sm + SOFF_HIDT;
    float2* gtab= (float2*)(sm + SOFF_GTAB);
    float* xg   = sm + SOFF_XG;
    float* mkf  = sm + SOFF_MK;
    float* sums = sm + SOFF_SUM;
    float* meanv= sm + SOFF_MEAN;
    float* istdv= sm + SOFF_ISTD;
    float* coefv= sm + SOFF_COEF;
    float* b1s  = sm + SOFF_B1;
    float* b2s  = sm + SOFF_B2;

    const int tid = threadIdx.x;
    const int b = blockIdx.x >> 8;
    const int i = blockIdx.x & 255;

    // ---- load weights into smem ----
    {
        const float4* w1g = (const float4*)w1;
        float4* w1d = (float4*)w1s;
        #pragma unroll 4
        for (int idx = tid; idx < (128*128)/4; idx += 256) w1d[idx] = w1g[idx];
        const float4* w2g = (const float4*)w2;
        float4* w2d = (float4*)w2s;
        #pragma unroll 2
        for (int idx = tid; idx < (128*32)/4; idx += 256) w2d[idx] = w2g[idx];
    }
    // ---- gelu Phi table ----
    for (int t = tid; t < 1024; t += 256) {
        float v0 = GVMIN + t * GSTEP;
        float p0 = 0.5f * (1.0f + erff(v0 * 0.70710678f));
        float p1 = 0.5f * (1.0f + erff((v0 + GSTEP) * 0.70710678f));
        gtab[t] = make_float2(p0, p1 - p0);
    }
    if (tid < 128) {
        float s = fabsf(stds[tid]) + 0.01f;
        float a = sqrtf(2.0f * 3.14159f);
        istdv[tid] = 1.0f / s;
        coefv[tid] = 1.0f / (a * s);
        meanv[tid] = means[tid];
        b1s[tid]   = b1[tid];
        sums[tid]  = 0.0f;
    }
    if (tid < 32) b2s[tid] = b2[tid];

    // ---- phase 0: per-j dist, delta_pos, xg, mask ----
    {
        const int j = tid;
        float pix = pos[(b*Nn + i)*3 + 0];
        float piy = pos[(b*Nn + i)*3 + 1];
        float piz = pos[(b*Nn + i)*3 + 2];
        float dx = pos[(b*Nn + j)*3 + 0] - pix;
        float dy = pos[(b*Nn + j)*3 + 1] - piy;
        float dz = pos[(b*Nn + j)*3 + 2] - piz;
        float dist = sqrtf(dx*dx + dy*dy + dz*dz + 1e-12f);
        float rn = 1.0f / (dist + 1e-5f);
        int dpb = OFF_DP + ((b*Nn + i)*Nn + j)*3;
        out[dpb + 0] = dx * rn;
        out[dpb + 1] = dy * rn;
        out[dpb + 2] = dz * rn;

        int eb = (((b*Nn + i)*Nn) + j)*2;
        int e0 = nte[eb], e1 = nte[eb + 1];
        float mu = mul_w[e0] + mul_w[e1];
        float bi = bias_w[e0] + bias_w[e1];
        xg[j] = mu * dist + bi;

        const int* xp = x + (b*Nn + j)*9;
        bool m = true;
        #pragma unroll
        for (int q = 0; q < 9; q++) m = m && (xp[q] == 0);
        mkf[j] = m ? 1.0f : 0.0f;
    }
    __syncthreads();

    const int ty = tid >> 4;        // 0..15, j-group of 8
    const int tx = tid & 15;        // 0..15, h-group of 8
    const int jg = tid & 63;        // 0..63, j-group of 2 (GEMM2)
    const int hg = tid >> 6;        // 0..3,  h2-group of 8 (GEMM2)
    const float NEG_INF = __int_as_float(0xff800000);

    for (int jt = 0; jt < 2; jt++) {
        const int j0 = jt * 128;

        // ---- gaussian edge features: efT[k][j], k-major ----
        {
            const int jl = tid & 127;
            const int kh = tid >> 7;
            const float xv = xg[j0 + jl];
            #pragma unroll 8
            for (int kk = 0; kk < 64; kk++) {
                int k = kh*64 + kk;
                float t = (xv - meanv[k]) * istdv[k];
                efT[k*128 + jl] = coefv[k] * __expf(-0.5f * t * t);
            }
        }
        __syncthreads();

        // ---- masked j-sum of edge features (threads < 128, diagonal read) ----
        if (tid < 128) {
            float acc = 0.0f;
            const float* row = &efT[tid*128];
            #pragma unroll 4
            for (int jj = 0; jj < 128; jj++) {
                int jl = (tid + jj) & 127;
                acc += row[jl] * (1.0f - mkf[j0 + jl]);
            }
            sums[tid] += acc;
        }

        // ---- GEMM1 (f32x2): hid[128j x 128h] = efT^T @ w1 + b1 ----
        // acc pairs packed along h: accp[u][v2] covers h = tx*8 + 2*v2 (+1)
        uint64_t accp[8][4];
        #pragma unroll
        for (int v2 = 0; v2 < 4; v2++) {
            uint64_t bp = *(const uint64_t*)&b1s[tx*8 + 2*v2];
            #pragma unroll
            for (int u = 0; u < 8; u++) accp[u][v2] = bp;
        }

        #pragma unroll 4
        for (int k = 0; k < 128; k++) {
            const float* efr = &efT[k*128 + ty*8];
            float4 a0 = *(const float4*)(efr);
            float4 a1 = *(const float4*)(efr + 4);
            const ulonglong2 wA = *(const ulonglong2*)&w1s[k*128 + tx*8];
            const ulonglong2 wB = *(const ulonglong2*)&w1s[k*128 + tx*8 + 4];
            uint64_t bp[4] = {wA.x, wA.y, wB.x, wB.y};
            float av[8] = {a0.x, a0.y, a0.z, a0.w, a1.x, a1.y, a1.z, a1.w};
            uint64_t au[8];
            #pragma unroll
            for (int u = 0; u < 8; u++) PACK2(au[u], av[u]);   // alu pipe
            #pragma unroll
            for (int u = 0; u < 8; u++)
                #pragma unroll
                for (int v2 = 0; v2 < 4; v2++)
                    FMA2(accp[u][v2], au[u], bp[v2]);          // fma pipe
        }

        // gelu + store transposed: hidT[h][j]
        #pragma unroll
        for (int v2 = 0; v2 < 4; v2++) {
            float lo[8], hi[8];
            #pragma unroll
            for (int u = 0; u < 8; u++) {
                float2 p = u2f(accp[u][v2]);
                lo[u] = gelu_tab(p.x, gtab);
                hi[u] = gelu_tab(p.y, gtab);
            }
            float* hr0 = &hidT[(tx*8 + 2*v2    )*128 + ty*8];
            float* hr1 = &hidT[(tx*8 + 2*v2 + 1)*128 + ty*8];
            *(float4*)(hr0)     = make_float4(lo[0], lo[1], lo[2], lo[3]);
            *(float4*)(hr0 + 4) = make_float4(lo[4], lo[5], lo[6], lo[7]);
            *(float4*)(hr1)     = make_float4(hi[0], hi[1], hi[2], hi[3]);
            *(float4*)(hr1 + 4) = make_float4(hi[4], hi[5], hi[6], hi[7]);
        }
        __syncthreads();

        // ---- GEMM2 (f32x2): gbf[128j x 32h2] = hid @ w2 + b2 ----
        // pairs along h2: acc2p[jj][v2] covers h2 = hg*8 + 2*v2 (+1)
        uint64_t acc2p[2][4];
        #pragma unroll
        for (int v2 = 0; v2 < 4; v2++) {
            uint64_t bp = *(const uint64_t*)&b2s[hg*8 + 2*v2];
            acc2p[0][v2] = bp; acc2p[1][v2] = bp;
        }
        #pragma unroll 4
        for (int h = 0; h < 128; h++) {
            float2 av = *(const float2*)&hidT[h*128 + jg*2];
            const ulonglong2 wA = *(const ulonglong2*)&w2s[h*32 + hg*8];
            const ulonglong2 wB = *(const ulonglong2*)&w2s[h*32 + hg*8 + 4];
            uint64_t bp[4] = {wA.x, wA.y, wB.x, wB.y};
            uint64_t au0, au1;
            PACK2(au0, av.x);
            PACK2(au1, av.y);
            #pragma unroll
            for (int v2 = 0; v2 < 4; v2++) {
                FMA2(acc2p[0][v2], au0, bp[v2]);
                FMA2(acc2p[1][v2], au1, bp[v2]);
            }
        }

        // write gbias[b][h2][i][j], masked -inf on padded j
        const float m0 = mkf[j0 + jg*2 + 0];
        const float m1 = mkf[j0 + jg*2 + 1];
        #pragma unroll
        for (int v2 = 0; v2 < 4; v2++) {
            float2 p0 = u2f(acc2p[0][v2]);   // j = jg*2,   h2 = hg*8+2v2, +1
            float2 p1 = u2f(acc2p[1][v2]);   // j = jg*2+1
            int h2a = hg*8 + 2*v2, h2b = h2a + 1;
            float va0 = (m0 > 0.5f) ? NEG_INF : p0.x;
            float vb0 = (m0 > 0.5f) ? NEG_INF : p0.y;
            float va1 = (m1 > 0.5f) ? NEG_INF : p1.x;
            float vb1 = (m1 > 0.5f) ? NEG_INF : p1.y;
            int offa = OFF_GB + (((b*Hh + h2a)*Nn + i)*Nn + j0 + jg*2);
            int offb = OFF_GB + (((b*Hh + h2b)*Nn + i)*Nn + j0 + jg*2);
            *(float2*)&out[offa] = make_float2(va0, va1);
            *(float2*)&out[offb] = make_float2(vb0, vb1);
        }
        __syncthreads();   // efT/hidT reused next tile
    }

    if (tid < 128) g_sum_ef[(b*Nn + i)*Kk + tid] = sums[tid];
}

// merge_edge_features = sum_ef @ edge_w + edge_b  ([2048,128] @ [128,768])
extern "C" __global__ void __launch_bounds__(256, 6)
mol3d_merge(const float* __restrict__ edge_w, const float* __restrict__ edge_b,
            float* __restrict__ out)
{
    __shared__ float sT[128*8];   // [k][r], 8 rows per block
    const int tid = threadIdx.x;
    const int r0 = blockIdx.x * 8;
    const int d  = blockIdx.y * 256 + tid;

    for (int idx = tid; idx < 8*128; idx += 256) {
        int r = idx >> 7, k = idx & 127;
        sT[k*8 + r] = g_sum_ef[(r0 + r)*128 + k];
    }
    __syncthreads();

    const float bb = edge_b[d];
    uint64_t accp[4];
    uint64_t bbp; PACK2(bbp, bb);
    #pragma unroll
    for (int v = 0; v < 4; v++) accp[v] = bbp;

    #pragma unroll 4
    for (int k = 0; k < 128; k++) {
        float w = edge_w[k*768 + d];
        uint64_t wp; PACK2(wp, w);
        const ulonglong2 s0 = *(const ulonglong2*)&sT[k*8];
        const ulonglong2 s1 = *(const ulonglong2*)&sT[k*8 + 4];
        FMA2(accp[0], wp, s0.x);
        FMA2(accp[1], wp, s0.y);
        FMA2(accp[2], wp, s1.x);
        FMA2(accp[3], wp, s1.y);
    }
    #pragma unroll
    for (int v = 0; v < 4; v++) {
        float2 p = u2f(accp[v]);
        out[OFF_MERGE + (r0 + 2*v    )*768 + d] = p.x;
        out[OFF_MERGE + (r0 + 2*v + 1)*768 + d] = p.y;
    }
}

extern "C" void kernel_launch(void* const* d_in, const int* in_sizes, int n_in,
                              void* d_out, int out_size)
{
    const float* pos    = (const float*)d_in[0];
    const int*   x      = (const int*)  d_in[1];
    const int*   nte    = (const int*)  d_in[2];
    const float* means  = (const float*)d_in[3];
    const float* stds   = (const float*)d_in[4];
    const float* mul_w  = (const float*)d_in[5];
    const float* bias_w = (const float*)d_in[6];
    const float* w1     = (const float*)d_in[7];
    const float* b1     = (const float*)d_in[8];
    const float* w2     = (const float*)d_in[9];
    const float* b2     = (const float*)d_in[10];
    const float* edge_w = (const float*)d_in[11];
    const float* edge_b = (const float*)d_in[12];
    float* out = (float*)d_out;

    const int smem_bytes = SMEM_FLOATS * 4;   // 225920
    cudaFuncSetAttribute((const void*)mol3d_main,
                         cudaFuncAttributeMaxDynamicSharedMemorySize, smem_bytes);

    mol3d_main<<<Bb*Nn, 256, smem_bytes>>>(pos, x, nte, means, stds, mul_w,
                                           bias_w, w1, b1, w2, b2, out);
    mol3d_merge<<<dim3(256, 3), 256>>>(edge_w, edge_b, out);
}